// round 1
// baseline (speedup 1.0000x reference)
#include <cuda_runtime.h>

// Problem dims
#define BB 8
#define AA 8
#define FF 512
#define HH 128
#define D  32
#define HID 256

// Row layout of the fused node buffer X:
// robot [0,64), frontier [64,4160), rh [4160,5184), fh [5184,6208)
#define OFF_R  0
#define OFF_F  64
#define OFF_RH 4160
#define OFF_FH 5184
#define R_TOT  6208

// Scratch (static device globals -- no runtime allocation)
__device__ float gX[R_TOT * D];
__device__ float gQ[R_TOT * D];
__device__ float gK[R_TOT * D];
__device__ float gV[R_TOT * D];
__device__ float gHq[4160 * HID];   // x-side edge-MLP partials
__device__ float gHk[4096 * HID];   // y-side edge-MLP partials (+eb1 folded)
__device__ float gYV[4096 * D];     // y-side value vectors

__device__ __forceinline__ float wredsum(float v) {
#pragma unroll
    for (int o = 16; o; o >>= 1) v += __shfl_xor_sync(0xffffffffu, v, o);
    return v;
}

// ---------------------------------------------------------------------------
// Node-init MLP: pos[3] -> 256 relu -> 32, for all 6208 nodes.
// ---------------------------------------------------------------------------
__global__ void k_init(const float* __restrict__ ap, const float* __restrict__ fp,
                       const float* __restrict__ pa, const float* __restrict__ pg,
                       const float* __restrict__ W1, const float* __restrict__ b1,
                       const float* __restrict__ W2, const float* __restrict__ b2) {
    int r = blockIdx.x, t = threadIdx.x;
    const float* src;
    if (r < OFF_F)        src = ap + r * 3;
    else if (r < OFF_RH)  src = fp + (r - OFF_F) * 3;
    else if (r < OFF_FH)  src = pa + (r - OFF_RH) * 3;
    else                  src = pg + (r - OFF_FH) * 3;
    float x0 = src[0], x1 = src[1], x2 = src[2];

    __shared__ float hh[HID];
    __shared__ float part[256];
    float h = fmaf(x0, W1[t], fmaf(x1, W1[256 + t], fmaf(x2, W1[512 + t], b1[t])));
    hh[t] = fmaxf(h, 0.0f);
    __syncthreads();

    int g = t >> 5, d = t & 31;
    float p = 0.0f;
#pragma unroll 8
    for (int j = g * 32; j < g * 32 + 32; ++j) p = fmaf(hh[j], W2[j * D + d], p);
    part[t] = p;
    __syncthreads();
    if (t < D) {
        float s = b2[t];
#pragma unroll
        for (int g2 = 0; g2 < 8; ++g2) s += part[g2 * 32 + t];
        gX[r * D + t] = s;
    }
}

// ---------------------------------------------------------------------------
// QKV projections for all rows (weights already offset to block b)
// ---------------------------------------------------------------------------
__global__ void k_qkv(const float* __restrict__ Wq, const float* __restrict__ bq,
                      const float* __restrict__ Wk, const float* __restrict__ bk,
                      const float* __restrict__ Wv, const float* __restrict__ bv) {
    int r = blockIdx.x, t = threadIdx.x;
    __shared__ float xs[D];
    if (t < D) xs[t] = gX[r * D + t];
    __syncthreads();
    int m = t >> 5, d = t & 31;
    const float* W  = (m == 0) ? Wq : (m == 1) ? Wk : Wv;
    const float* bb = (m == 0) ? bq : (m == 1) ? bk : bv;
    float acc = bb[d];
#pragma unroll
    for (int c = 0; c < D; ++c) acc = fmaf(xs[c], W[c * D + d], acc);
    float* out = (m == 0) ? gQ : (m == 1) ? gK : gV;
    out[r * D + d] = acc;
}

// ---------------------------------------------------------------------------
// Intra self-attention + node MLP + residual, one block per row, all 4 sets
// ---------------------------------------------------------------------------
__global__ void k_intra(const float* __restrict__ nW1, const float* __restrict__ nb1,
                        const float* __restrict__ nW2, const float* __restrict__ nb2) {
    int r = blockIdx.x, t = threadIdx.x;
    int wid = t >> 5, lane = t & 31;
    int N, base;
    if (r < OFF_F)        { N = AA; base = r & ~(AA - 1); }
    else if (r < OFF_RH)  { N = FF; int f = r - OFF_F;  base = OFF_F  + (f & ~(FF - 1)); }
    else if (r < OFF_FH)  { N = HH; int f = r - OFF_RH; base = OFF_RH + (f & ~(HH - 1)); }
    else                  { N = HH; int f = r - OFF_FH; base = OFF_FH + (f & ~(HH - 1)); }

    __shared__ float qs[D];
    __shared__ float sc[512];
    __shared__ float part[256];
    __shared__ float red[256];
    __shared__ float zz[2 * D];
    __shared__ float hh[HID];

    if (t < D) qs[t] = gQ[r * D + t];
    __syncthreads();

    // scores: one j per warp iteration, dot-32 via shuffle reduce
    for (int j = wid; j < N; j += 8) {
        float v = qs[lane] * gK[(base + j) * D + lane];
        v = wredsum(v);
        if (lane == 0) sc[j] = v;
    }
    __syncthreads();

    // softmax over j
    float m = -1e30f;
    for (int j = t; j < N; j += 256) m = fmaxf(m, sc[j]);
    red[t] = m; __syncthreads();
    for (int o = 128; o; o >>= 1) { if (t < o) red[t] = fmaxf(red[t], red[t + o]); __syncthreads(); }
    m = red[0]; __syncthreads();
    float ls = 0.0f;
    for (int j = t; j < N; j += 256) { float e = __expf(sc[j] - m); sc[j] = e; ls += e; }
    red[t] = ls; __syncthreads();
    for (int o = 128; o; o >>= 1) { if (t < o) red[t] += red[t + o]; __syncthreads(); }
    float inv = 1.0f / red[0]; __syncthreads();

    // agg[d] = sum_j p_j * V[j][d]
    float a = 0.0f;
    for (int j = wid; j < N; j += 8) a = fmaf(sc[j], gV[(base + j) * D + lane], a);
    part[t] = a; __syncthreads();
    if (t < D) {
        float s = 0.0f;
#pragma unroll
        for (int g2 = 0; g2 < 8; ++g2) s += part[g2 * 32 + t];
        zz[D + t] = s * inv;
        zz[t] = gX[r * D + t];
    }
    __syncthreads();

    // node MLP: concat 64 -> 256 relu -> 32, residual
    float acc = nb1[t];
#pragma unroll 8
    for (int c = 0; c < 2 * D; ++c) acc = fmaf(zz[c], nW1[c * HID + t], acc);
    hh[t] = fmaxf(acc, 0.0f);
    __syncthreads();
    float p = 0.0f;
#pragma unroll 8
    for (int j = wid * 32; j < wid * 32 + 32; ++j) p = fmaf(hh[j], nW2[j * D + lane], p);
    part[t] = p;
    __syncthreads();
    if (t < D) {
        float s = nb2[t];
#pragma unroll
        for (int g2 = 0; g2 < 8; ++g2) s += part[g2 * 32 + t];
        gX[r * D + t] = zz[t] + s;
    }
}

// ---------------------------------------------------------------------------
// Inter prep: x-rows -> gHq ; y-rows -> gHk (+eb1) and gYV
// phase 0: x = robot+frontier (idx<4160), y = rh+fh (idx>=4160)
// phase 1: x = robot (idx<64),            y = frontier (idx>=64)
// ---------------------------------------------------------------------------
__global__ void k_prep(int phase,
                       const float* __restrict__ Wq, const float* __restrict__ bq,
                       const float* __restrict__ Wk, const float* __restrict__ bk,
                       const float* __restrict__ Wv, const float* __restrict__ bv,
                       const float* __restrict__ eW1, const float* __restrict__ eb1) {
    int idx = blockIdx.x, t = threadIdx.x;
    int isX, xrow, hrow;
    if (phase == 0) {
        if (idx < 4160) { isX = 1; xrow = idx; hrow = idx; }
        else            { isX = 0; xrow = idx; hrow = idx - 4160; }
    } else {
        if (idx < 64)   { isX = 1; xrow = idx; hrow = idx; }
        else            { isX = 0; xrow = idx; hrow = idx - 64; }
    }
    __shared__ float xs[D];
    __shared__ float pr[D];
    if (t < D) xs[t] = gX[xrow * D + t];
    __syncthreads();
    if (isX) {
        if (t < D) {
            float acc = bq[t];
#pragma unroll
            for (int c = 0; c < D; ++c) acc = fmaf(xs[c], Wq[c * D + t], acc);
            pr[t] = acc;
        }
        __syncthreads();
        float h = 0.0f;
#pragma unroll
        for (int c = 0; c < D; ++c) h = fmaf(pr[c], eW1[c * HID + t], h);
        gHq[hrow * HID + t] = h;
    } else {
        if (t < D) {
            float acc = bk[t];
#pragma unroll
            for (int c = 0; c < D; ++c) acc = fmaf(xs[c], Wk[c * D + t], acc);
            pr[t] = acc;
        } else if (t < 2 * D) {
            int d = t - D;
            float acc = bv[d];
#pragma unroll
            for (int c = 0; c < D; ++c) acc = fmaf(xs[c], Wv[c * D + d], acc);
            gYV[hrow * D + d] = acc;
        }
        __syncthreads();
        float h = eb1[t];
#pragma unroll
        for (int c = 0; c < D; ++c) h = fmaf(pr[c], eW1[(D + c) * HID + t], h);
        gHk[hrow * HID + t] = h;
    }
}

// ---------------------------------------------------------------------------
// Inter main: edge-MLP scores + softmax + agg + node MLP (or edge write)
// phase 0 grid 4160: robot rows (Ny=128, rh) + frontier rows (Ny=128, fh)
// phase 1 grid 64:   robot rows (Ny=512, frontier); last block writes edge
// ---------------------------------------------------------------------------
__global__ void k_main(int phase,
                       const float* __restrict__ disRP, const float* __restrict__ disFP,
                       const float* __restrict__ disRF,
                       const float* __restrict__ eW1, const float* __restrict__ eW2,
                       const float* __restrict__ eb2,
                       const float* __restrict__ nW1, const float* __restrict__ nb1,
                       const float* __restrict__ nW2, const float* __restrict__ nb2,
                       float* edgeOut, int doMLP) {
    int idx = blockIdx.x, t = threadIdx.x;
    int wid = t >> 5, lane = t & 31;
    int Ny, hkbase, xrow, hqrow;
    const float* dis;
    if (phase == 0) {
        if (idx < 64) {
            int b = idx >> 3, il = idx & 7;
            Ny = HH; hkbase = b * HH; dis = disRP + (b * AA + il) * HH;
        } else {
            int f = idx - 64; int b = f >> 9, il = f & 511;
            Ny = HH; hkbase = 1024 + b * HH; dis = disFP + (b * FF + il) * HH;
        }
        xrow = idx; hqrow = idx;
    } else {
        int b = idx >> 3, il = idx & 7;
        Ny = FF; hkbase = b * FF; dis = disRF + (b * AA + il) * FF;
        xrow = idx; hqrow = idx;
    }

    __shared__ float hqs[HID], wd[HID], e2[HID];
    __shared__ float sc[512], part[256], red[256], zz[2 * D], hh[HID];

    hqs[t] = gHq[hqrow * HID + t];
    wd[t]  = eW1[64 * HID + t];
    e2[t]  = eW2[t];
    float eb2v = eb2[0];
    __syncthreads();

    // scores
    for (int j = wid; j < Ny; j += 8) {
        float dij = __ldg(dis + j);
        const float* hk = gHk + (hkbase + j) * HID;
        float acc = 0.0f;
#pragma unroll
        for (int u = 0; u < 8; ++u) {
            int d = lane + 32 * u;
            float hv = hqs[d] + hk[d] + dij * wd[d];
            hv = fmaxf(hv, 0.0f);
            acc = fmaf(hv, e2[d], acc);
        }
        acc = wredsum(acc);
        if (lane == 0) sc[j] = acc + eb2v;
    }
    __syncthreads();

    // softmax
    float m = -1e30f;
    for (int j = t; j < Ny; j += 256) m = fmaxf(m, sc[j]);
    red[t] = m; __syncthreads();
    for (int o = 128; o; o >>= 1) { if (t < o) red[t] = fmaxf(red[t], red[t + o]); __syncthreads(); }
    m = red[0]; __syncthreads();
    float ls = 0.0f;
    for (int j = t; j < Ny; j += 256) { float e = __expf(sc[j] - m); sc[j] = e; ls += e; }
    red[t] = ls; __syncthreads();
    for (int o = 128; o; o >>= 1) { if (t < o) red[t] += red[t + o]; __syncthreads(); }
    float inv = 1.0f / red[0]; __syncthreads();

    if (edgeOut != nullptr) {
        float* eo = edgeOut + idx * FF;
        for (int j = t; j < Ny; j += 256) eo[j] = sc[j] * inv;
    }
    if (!doMLP) return;

    // agg
    float a = 0.0f;
    for (int j = wid; j < Ny; j += 8) a = fmaf(sc[j], gYV[(hkbase + j) * D + lane], a);
    part[t] = a; __syncthreads();
    if (t < D) {
        float s = 0.0f;
#pragma unroll
        for (int g2 = 0; g2 < 8; ++g2) s += part[g2 * 32 + t];
        zz[D + t] = s * inv;
        zz[t] = gX[xrow * D + t];
    }
    __syncthreads();

    // node MLP + residual
    float acc = nb1[t];
#pragma unroll 8
    for (int c = 0; c < 2 * D; ++c) acc = fmaf(zz[c], nW1[c * HID + t], acc);
    hh[t] = fmaxf(acc, 0.0f);
    __syncthreads();
    float p = 0.0f;
#pragma unroll 8
    for (int j = wid * 32; j < wid * 32 + 32; ++j) p = fmaf(hh[j], nW2[j * D + lane], p);
    part[t] = p;
    __syncthreads();
    if (t < D) {
        float s = nb2[t];
#pragma unroll
        for (int g2 = 0; g2 < 8; ++g2) s += part[g2 * 32 + t];
        gX[xrow * D + t] = zz[t] + s;
    }
}

// ---------------------------------------------------------------------------
extern "C" void kernel_launch(void* const* d_in, const int* in_sizes, int n_in,
                              void* d_out, int out_size) {
    const float* agent_pos    = (const float*)d_in[0];
    const float* frontier_pos = (const float*)d_in[1];
    const float* past_agent   = (const float*)d_in[2];
    const float* past_goal    = (const float*)d_in[3];
    const float* dis_rp       = (const float*)d_in[4];
    const float* dis_fp       = (const float*)d_in[5];
    const float* dis_rf       = (const float*)d_in[6];
    const float* ni_W1        = (const float*)d_in[7];
    const float* ni_b1        = (const float*)d_in[8];
    const float* ni_W2        = (const float*)d_in[9];
    const float* ni_b2        = (const float*)d_in[10];
    const float* Wq           = (const float*)d_in[11];
    const float* bq           = (const float*)d_in[12];
    const float* Wk           = (const float*)d_in[13];
    const float* bk           = (const float*)d_in[14];
    const float* Wv           = (const float*)d_in[15];
    const float* bv           = (const float*)d_in[16];
    const float* nW1          = (const float*)d_in[17];
    const float* nb1          = (const float*)d_in[18];
    const float* nW2          = (const float*)d_in[19];
    const float* nb2          = (const float*)d_in[20];
    const float* eW1          = (const float*)d_in[21];
    const float* eb1          = (const float*)d_in[22];
    const float* eW2          = (const float*)d_in[23];
    const float* eb2          = (const float*)d_in[24];
    float* edge = (float*)d_out;

    k_init<<<R_TOT, 256>>>(agent_pos, frontier_pos, past_agent, past_goal,
                           ni_W1, ni_b1, ni_W2, ni_b2);

    for (int b3 = 0; b3 < 3; ++b3) {
        const float* Wq_b  = Wq  + b3 * 32 * 32;
        const float* bq_b  = bq  + b3 * 32;
        const float* Wk_b  = Wk  + b3 * 32 * 32;
        const float* bk_b  = bk  + b3 * 32;
        const float* Wv_b  = Wv  + b3 * 32 * 32;
        const float* bv_b  = bv  + b3 * 32;
        const float* nW1_b = nW1 + b3 * 64 * 256;
        const float* nb1_b = nb1 + b3 * 256;
        const float* nW2_b = nW2 + b3 * 256 * 32;
        const float* nb2_b = nb2 + b3 * 32;
        const float* eW1_b = eW1 + b3 * 65 * 256;
        const float* eb1_b = eb1 + b3 * 256;
        const float* eW2_b = eW2 + b3 * 256;
        const float* eb2_b = eb2 + b3;

        k_qkv<<<R_TOT, 96>>>(Wq_b, bq_b, Wk_b, bk_b, Wv_b, bv_b);
        k_intra<<<R_TOT, 256>>>(nW1_b, nb1_b, nW2_b, nb2_b);

        // phase A: inter(robot, rh) + inter(frontier, fh) fused
        k_prep<<<R_TOT, 256>>>(0, Wq_b, bq_b, Wk_b, bk_b, Wv_b, bv_b, eW1_b, eb1_b);
        k_main<<<4160, 256>>>(0, dis_rp, dis_fp, dis_rf, eW1_b, eW2_b, eb2_b,
                              nW1_b, nb1_b, nW2_b, nb2_b, nullptr, 1);

        // phase B: inter(robot, frontier)
        k_prep<<<4160, 256>>>(1, Wq_b, bq_b, Wk_b, bk_b, Wv_b, bv_b, eW1_b, eb1_b);
        float* eo = (b3 == 2) ? edge : nullptr;
        int doMLP = (b3 == 2) ? 0 : 1;
        k_main<<<64, 256>>>(1, dis_rp, dis_fp, dis_rf, eW1_b, eW2_b, eb2_b,
                            nW1_b, nb1_b, nW2_b, nb2_b, eo, doMLP);
    }
}

// round 2
// speedup vs baseline: 1.8960x; 1.8960x over previous
#include <cuda_runtime.h>

#define BB 8
#define AA 8
#define FF 512
#define HH 128
#define D  32
#define HID 256

// Row layout of fused node buffer X:
#define OFF_R  0
#define OFF_F  64
#define OFF_RH 4160
#define OFF_FH 5184
#define R_TOT  6208

#define FULL 0xffffffffu

// Static device scratch
__device__ float gX[R_TOT * D];
__device__ float gQ[R_TOT * D];
__device__ float gK[R_TOT * D];
__device__ float gV[R_TOT * D];
__device__ float gHk[2048 * HID];    // phase A y-side hidden partial (+eb1): rh [0,1024), fh [1024,2048)
__device__ float gYV[2048 * D];      // phase A y values
__device__ float gHkB[4096 * HID];   // phase B y-side (frontier)
__device__ float gYVB[4096 * D];

__device__ __forceinline__ float red8(float v) {
    v += __shfl_xor_sync(FULL, v, 1);
    v += __shfl_xor_sync(FULL, v, 2);
    v += __shfl_xor_sync(FULL, v, 4);
    return v;
}
__device__ __forceinline__ float red32(float v) {
#pragma unroll
    for (int o = 16; o; o >>= 1) v += __shfl_xor_sync(FULL, v, o);
    return v;
}
__device__ __forceinline__ float rmax32(float v) {
#pragma unroll
    for (int o = 16; o; o >>= 1) v = fmaxf(v, __shfl_xor_sync(FULL, v, o));
    return v;
}

// ---------------------------------------------------------------------------
// Node-init MLP, warp-per-row (8 rows per block)
// ---------------------------------------------------------------------------
__global__ void __launch_bounds__(256) k_init(
    const float* __restrict__ ap, const float* __restrict__ fp,
    const float* __restrict__ pa, const float* __restrict__ pg,
    const float* __restrict__ W1, const float* __restrict__ b1,
    const float* __restrict__ W2, const float* __restrict__ b2) {
    __shared__ float hw[8][256];
    int w = threadIdx.x >> 5, l = threadIdx.x & 31;
    int r = blockIdx.x * 8 + w;
    const float* src;
    if (r < OFF_F)        src = ap + r * 3;
    else if (r < OFF_RH)  src = fp + (r - OFF_F) * 3;
    else if (r < OFF_FH)  src = pa + (r - OFF_RH) * 3;
    else                  src = pg + (r - OFF_FH) * 3;
    float x0 = src[0], x1 = src[1], x2 = src[2];
#pragma unroll
    for (int u = 0; u < 8; ++u) {
        int d = u * 32 + l;
        float h = fmaf(x0, W1[d], fmaf(x1, W1[256 + d], fmaf(x2, W1[512 + d], b1[d])));
        hw[w][d] = fmaxf(h, 0.0f);
    }
    __syncwarp();
    float acc = b2[l];
#pragma unroll 8
    for (int j = 0; j < 256; ++j) acc = fmaf(hw[w][j], W2[j * 32 + l], acc);
    gX[r * 32 + l] = acc;
}

// ---------------------------------------------------------------------------
// QKV projections, warp-per-row
// ---------------------------------------------------------------------------
__global__ void __launch_bounds__(256) k_qkv(
    const float* __restrict__ Wq, const float* __restrict__ bq,
    const float* __restrict__ Wk, const float* __restrict__ bk,
    const float* __restrict__ Wv, const float* __restrict__ bv) {
    int w = threadIdx.x >> 5, l = threadIdx.x & 31;
    int r = blockIdx.x * 8 + w;
    float x = gX[r * 32 + l];
    float aq = bq[l], ak = bk[l], av = bv[l];
#pragma unroll
    for (int c = 0; c < 32; ++c) {
        float xb = __shfl_sync(FULL, x, c);
        aq = fmaf(xb, Wq[c * 32 + l], aq);
        ak = fmaf(xb, Wk[c * 32 + l], ak);
        av = fmaf(xb, Wv[c * 32 + l], av);
    }
    gQ[r * 32 + l] = aq; gK[r * 32 + l] = ak; gV[r * 32 + l] = av;
}

// ---------------------------------------------------------------------------
// Intra attention, TI=8 rows per block, + fused y-side prep for rh/fh rows
// blocks: [0,8) robot  [8,520) frontier  [520,648) rh  [648,776) fh
// ---------------------------------------------------------------------------
__global__ void __launch_bounds__(256) k_intra(
    const float* __restrict__ nW1, const float* __restrict__ nb1,
    const float* __restrict__ nW2, const float* __restrict__ nb2,
    const float* __restrict__ Wk, const float* __restrict__ bk,
    const float* __restrict__ Wv, const float* __restrict__ bv,
    const float* __restrict__ eW1, const float* __restrict__ eb1) {
    __shared__ __align__(16) float qs[8][32];
    __shared__ float sc[8][512];
    __shared__ float partA[8][8][32];
    __shared__ __align__(16) float xa[64][8];
    __shared__ float hh[8][256];
    __shared__ float inv[8];

    int t = threadIdx.x, w = t >> 5, l = t & 31;
    int blk = blockIdx.x;
    int base, N, r0;
    if (blk < 8)        { base = blk * 8; N = 8; r0 = base; }
    else if (blk < 520) { int f = blk - 8;   int b = f >> 6, tl = f & 63; base = OFF_F  + b * 512; N = 512; r0 = base + tl * 8; }
    else if (blk < 648) { int g = blk - 520; int b = g >> 4, tl = g & 15; base = OFF_RH + b * 128; N = 128; r0 = base + tl * 8; }
    else                { int g = blk - 648; int b = g >> 4, tl = g & 15; base = OFF_FH + b * 128; N = 128; r0 = base + tl * 8; }

    qs[w][l] = gQ[(r0 + w) * 32 + l];
    __syncthreads();

    // scores: subwarp-8 groups, 4 j per warp in flight
    int sl = l & 7, slot = w * 4 + (l >> 3);
    for (int jj = slot; jj < N; jj += 32) {
        float4 k4 = *(const float4*)(gK + (base + jj) * 32 + sl * 4);
#pragma unroll
        for (int i = 0; i < 8; ++i) {
            float4 q4 = *(const float4*)&qs[i][sl * 4];
            float acc = q4.x * k4.x + q4.y * k4.y + q4.z * k4.z + q4.w * k4.w;
            acc = red8(acc);
            if (sl == 0) sc[i][jj] = acc;
        }
    }
    __syncthreads();

    // softmax: warp-per-i
    {
        int i = w;
        float m = -1e30f;
        for (int j = l; j < N; j += 32) m = fmaxf(m, sc[i][j]);
        m = rmax32(m);
        float s = 0.0f;
        for (int j = l; j < N; j += 32) { float e = __expf(sc[i][j] - m); sc[i][j] = e; s += e; }
        s = red32(s);
        if (l == 0) inv[i] = 1.0f / s;
    }
    __syncthreads();

    // agg: warps split j, 8 accumulators
    {
        float ac[8];
#pragma unroll
        for (int i = 0; i < 8; ++i) ac[i] = 0.0f;
        for (int j = w; j < N; j += 8) {
            float v = gV[(base + j) * 32 + l];
#pragma unroll
            for (int i = 0; i < 8; ++i) ac[i] = fmaf(sc[i][j], v, ac[i]);
        }
#pragma unroll
        for (int i = 0; i < 8; ++i) partA[w][i][l] = ac[i];
    }
    __syncthreads();
    {
        int i = w;
        float s = 0.0f;
#pragma unroll
        for (int ww = 0; ww < 8; ++ww) s += partA[ww][i][l];
        xa[32 + l][i] = s * inv[i];
        xa[l][i] = gX[(r0 + i) * 32 + l];
    }
    __syncthreads();

    // node MLP stage1: each thread computes hidden[t] for 8 rows
    {
        float h8[8];
        float bb = nb1[t];
#pragma unroll
        for (int i = 0; i < 8; ++i) h8[i] = bb;
#pragma unroll 4
        for (int c = 0; c < 64; ++c) {
            float w1 = nW1[c * 256 + t];
            float4 a0 = *(const float4*)&xa[c][0];
            float4 a1 = *(const float4*)&xa[c][4];
            h8[0] = fmaf(a0.x, w1, h8[0]); h8[1] = fmaf(a0.y, w1, h8[1]);
            h8[2] = fmaf(a0.z, w1, h8[2]); h8[3] = fmaf(a0.w, w1, h8[3]);
            h8[4] = fmaf(a1.x, w1, h8[4]); h8[5] = fmaf(a1.y, w1, h8[5]);
            h8[6] = fmaf(a1.z, w1, h8[6]); h8[7] = fmaf(a1.w, w1, h8[7]);
        }
#pragma unroll
        for (int i = 0; i < 8; ++i) hh[i][t] = fmaxf(h8[i], 0.0f);
    }
    __syncthreads();

    // stage2: warp-per-i output + residual + fused y-prep
    {
        int i = w;
        float acc = nb2[l];
#pragma unroll 8
        for (int j = 0; j < 256; ++j) acc = fmaf(hh[i][j], nW2[j * 32 + l], acc);
        float xn = xa[l][i] + acc;
        int r = r0 + i;
        gX[r * 32 + l] = xn;
        if (r >= OFF_RH) {  // rh/fh rows: emit hk, yv for phase A
            int hr = r - OFF_RH;
            float yk = bk[l], yv = bv[l];
#pragma unroll
            for (int c = 0; c < 32; ++c) {
                float xb = __shfl_sync(FULL, xn, c);
                yk = fmaf(xb, Wk[c * 32 + l], yk);
                yv = fmaf(xb, Wv[c * 32 + l], yv);
            }
            gYV[hr * 32 + l] = yv;
            float hk[8];
#pragma unroll
            for (int u = 0; u < 8; ++u) hk[u] = eb1[u * 32 + l];
#pragma unroll
            for (int c = 0; c < 32; ++c) {
                float ykb = __shfl_sync(FULL, yk, c);
                const float* e1 = eW1 + (32 + c) * 256;
#pragma unroll
                for (int u = 0; u < 8; ++u) hk[u] = fmaf(ykb, e1[u * 32 + l], hk[u]);
            }
#pragma unroll
            for (int u = 0; u < 8; ++u) gHk[hr * 256 + u * 32 + l] = hk[u];
        }
    }
}

// ---------------------------------------------------------------------------
// Inter phase A: robot-vs-rh (blocks 0..7) + frontier-vs-fh (blocks 8..519)
// TI=8 x-rows per block, Ny=128. Fused x-side hq + frontier phase-B prep.
// ---------------------------------------------------------------------------
__global__ void __launch_bounds__(256) k_mainA(
    const float* __restrict__ disRP, const float* __restrict__ disFP,
    const float* __restrict__ Wq, const float* __restrict__ bq,
    const float* __restrict__ Wk, const float* __restrict__ bk,
    const float* __restrict__ Wv, const float* __restrict__ bv,
    const float* __restrict__ eW1, const float* __restrict__ eb1,
    const float* __restrict__ eW2, const float* __restrict__ eb2,
    const float* __restrict__ nW1, const float* __restrict__ nb1,
    const float* __restrict__ nW2, const float* __restrict__ nb2) {
    __shared__ __align__(16) float hqs[8][256];
    __shared__ float dt[1024];
    __shared__ float sc[8][128];
    __shared__ float partA[8][8][32];
    __shared__ __align__(16) float xa[64][8];
    __shared__ float hh[8][256];
    __shared__ float inv[8];

    int t = threadIdx.x, w = t >> 5, l = t & 31;
    int blk = blockIdx.x;
    int xrow0, hkbase, isF;
    const float* disrow;
    if (blk < 8) { xrow0 = blk * 8; hkbase = blk * 128; isF = 0; disrow = disRP + blk * 8 * 128; }
    else {
        int f = blk - 8; int b = f >> 6, tl = f & 63;
        xrow0 = OFF_F + b * 512 + tl * 8; hkbase = 1024 + b * 128; isF = 1;
        disrow = disFP + (b * 512 + tl * 8) * 128;
    }

    // x-side: xq = X@Wq+bq ; hq = xq@eW1[0:32]  (warp-per-i)
    {
        int i = w;
        float x = gX[(xrow0 + i) * 32 + l];
        float xq = bq[l];
#pragma unroll
        for (int c = 0; c < 32; ++c) xq = fmaf(__shfl_sync(FULL, x, c), Wq[c * 32 + l], xq);
        float hq[8];
#pragma unroll
        for (int u = 0; u < 8; ++u) hq[u] = 0.0f;
#pragma unroll
        for (int c = 0; c < 32; ++c) {
            float xqb = __shfl_sync(FULL, xq, c);
            const float* e1 = eW1 + c * 256;
#pragma unroll
            for (int u = 0; u < 8; ++u) hq[u] = fmaf(xqb, e1[u * 32 + l], hq[u]);
        }
#pragma unroll
        for (int u = 0; u < 8; ++u) hqs[i][u * 32 + l] = hq[u];
    }
    // dij tile (rows contiguous)
    for (int idx = t; idx < 1024; idx += 256) dt[idx] = disrow[idx];

    int sl = l & 7, slot = w * 4 + (l >> 3);
    float4 wd4[8], e24[8];
    {
        const float4* wdp = (const float4*)(eW1 + 64 * 256);
        const float4* e2p = (const float4*)eW2;
#pragma unroll
        for (int u = 0; u < 8; ++u) { wd4[u] = wdp[sl + 8 * u]; e24[u] = e2p[sl + 8 * u]; }
    }
    float eb2v = eb2[0];
    __syncthreads();

    // scores
    for (int jj = slot; jj < 128; jj += 32) {
        const float4* hkp = (const float4*)(gHk + (hkbase + jj) * 256);
        float4 hk4[8];
#pragma unroll
        for (int u = 0; u < 8; ++u) hk4[u] = hkp[sl + 8 * u];
#pragma unroll 1
        for (int i = 0; i < 8; ++i) {
            float dij = dt[i * 128 + jj];
            float acc = 0.0f;
#pragma unroll
            for (int u = 0; u < 8; ++u) {
                float4 q4 = *(const float4*)&hqs[i][sl * 4 + 32 * u];
                float hx = fmaxf(fmaf(dij, wd4[u].x, q4.x + hk4[u].x), 0.0f);
                float hy = fmaxf(fmaf(dij, wd4[u].y, q4.y + hk4[u].y), 0.0f);
                float hz = fmaxf(fmaf(dij, wd4[u].z, q4.z + hk4[u].z), 0.0f);
                float hw_ = fmaxf(fmaf(dij, wd4[u].w, q4.w + hk4[u].w), 0.0f);
                acc = fmaf(hx, e24[u].x, acc);
                acc = fmaf(hy, e24[u].y, acc);
                acc = fmaf(hz, e24[u].z, acc);
                acc = fmaf(hw_, e24[u].w, acc);
            }
            acc = red8(acc);
            if (sl == 0) sc[i][jj] = acc + eb2v;
        }
    }
    __syncthreads();

    // softmax warp-per-i
    {
        int i = w;
        float m = -1e30f;
#pragma unroll
        for (int k = 0; k < 4; ++k) m = fmaxf(m, sc[i][l + 32 * k]);
        m = rmax32(m);
        float s = 0.0f;
#pragma unroll
        for (int k = 0; k < 4; ++k) {
            float e = __expf(sc[i][l + 32 * k] - m);
            sc[i][l + 32 * k] = e; s += e;
        }
        s = red32(s);
        if (l == 0) inv[i] = 1.0f / s;
    }
    __syncthreads();

    // agg
    {
        float ac[8];
#pragma unroll
        for (int i = 0; i < 8; ++i) ac[i] = 0.0f;
        for (int j = w; j < 128; j += 8) {
            float v = gYV[(hkbase + j) * 32 + l];
#pragma unroll
            for (int i = 0; i < 8; ++i) ac[i] = fmaf(sc[i][j], v, ac[i]);
        }
#pragma unroll
        for (int i = 0; i < 8; ++i) partA[w][i][l] = ac[i];
    }
    __syncthreads();
    {
        int i = w;
        float s = 0.0f;
#pragma unroll
        for (int ww = 0; ww < 8; ++ww) s += partA[ww][i][l];
        xa[32 + l][i] = s * inv[i];
        xa[l][i] = gX[(xrow0 + i) * 32 + l];
    }
    __syncthreads();

    // node MLP stage1
    {
        float h8[8];
        float bb = nb1[t];
#pragma unroll
        for (int i = 0; i < 8; ++i) h8[i] = bb;
#pragma unroll 4
        for (int c = 0; c < 64; ++c) {
            float w1 = nW1[c * 256 + t];
            float4 a0 = *(const float4*)&xa[c][0];
            float4 a1 = *(const float4*)&xa[c][4];
            h8[0] = fmaf(a0.x, w1, h8[0]); h8[1] = fmaf(a0.y, w1, h8[1]);
            h8[2] = fmaf(a0.z, w1, h8[2]); h8[3] = fmaf(a0.w, w1, h8[3]);
            h8[4] = fmaf(a1.x, w1, h8[4]); h8[5] = fmaf(a1.y, w1, h8[5]);
            h8[6] = fmaf(a1.z, w1, h8[6]); h8[7] = fmaf(a1.w, w1, h8[7]);
        }
#pragma unroll
        for (int i = 0; i < 8; ++i) hh[i][t] = fmaxf(h8[i], 0.0f);
    }
    __syncthreads();

    // stage2 + phase-B prep for frontier rows
    {
        int i = w;
        float acc = nb2[l];
#pragma unroll 8
        for (int j = 0; j < 256; ++j) acc = fmaf(hh[i][j], nW2[j * 32 + l], acc);
        float xn = xa[l][i] + acc;
        gX[(xrow0 + i) * 32 + l] = xn;
        if (isF) {
            int hr = xrow0 - OFF_F + i;
            float yk = bk[l], yv = bv[l];
#pragma unroll
            for (int c = 0; c < 32; ++c) {
                float xb = __shfl_sync(FULL, xn, c);
                yk = fmaf(xb, Wk[c * 32 + l], yk);
                yv = fmaf(xb, Wv[c * 32 + l], yv);
            }
            gYVB[hr * 32 + l] = yv;
            float hk[8];
#pragma unroll
            for (int u = 0; u < 8; ++u) hk[u] = eb1[u * 32 + l];
#pragma unroll
            for (int c = 0; c < 32; ++c) {
                float ykb = __shfl_sync(FULL, yk, c);
                const float* e1 = eW1 + (32 + c) * 256;
#pragma unroll
                for (int u = 0; u < 8; ++u) hk[u] = fmaf(ykb, e1[u * 32 + l], hk[u]);
            }
#pragma unroll
            for (int u = 0; u < 8; ++u) gHkB[hr * 256 + u * 32 + l] = hk[u];
        }
    }
}

// ---------------------------------------------------------------------------
// Inter phase B: robot-vs-frontier, one block per robot row (64 blocks)
// ---------------------------------------------------------------------------
__global__ void __launch_bounds__(256) k_mainB(
    const float* __restrict__ disRF,
    const float* __restrict__ Wq, const float* __restrict__ bq,
    const float* __restrict__ eW1, const float* __restrict__ eW2,
    const float* __restrict__ eb2,
    const float* __restrict__ nW1, const float* __restrict__ nb1,
    const float* __restrict__ nW2, const float* __restrict__ nb2,
    float* edgeOut, int doMLP) {
    __shared__ __align__(16) float hqs[256];
    __shared__ float dt[512];
    __shared__ float sc[512];
    __shared__ float redm[8];
    __shared__ float reds[8];
    __shared__ float part[256];
    __shared__ float zz[64];
    __shared__ float hh[256];

    int t = threadIdx.x, w = t >> 5, l = t & 31;
    int idx = blockIdx.x;
    int b = idx >> 3;

    // x-side hq: each warp computes xq redundantly, then its own 32-chunk of hq
    {
        float x = gX[idx * 32 + l];
        float xq = bq[l];
#pragma unroll
        for (int c = 0; c < 32; ++c) xq = fmaf(__shfl_sync(FULL, x, c), Wq[c * 32 + l], xq);
        float h = 0.0f;
#pragma unroll
        for (int c = 0; c < 32; ++c)
            h = fmaf(__shfl_sync(FULL, xq, c), eW1[c * 256 + w * 32 + l], h);
        hqs[w * 32 + l] = h;
    }
    for (int j = t; j < 512; j += 256) dt[j] = disRF[idx * 512 + j];

    int sl = l & 7, slot = w * 4 + (l >> 3);
    float4 wd4[8], e24[8];
    {
        const float4* wdp = (const float4*)(eW1 + 64 * 256);
        const float4* e2p = (const float4*)eW2;
#pragma unroll
        for (int u = 0; u < 8; ++u) { wd4[u] = wdp[sl + 8 * u]; e24[u] = e2p[sl + 8 * u]; }
    }
    float eb2v = eb2[0];
    __syncthreads();

    // scores (Ny=512)
    for (int jj = slot; jj < 512; jj += 32) {
        const float4* hkp = (const float4*)(gHkB + (b * 512 + jj) * 256);
        float dij = dt[jj];
        float acc = 0.0f;
#pragma unroll
        for (int u = 0; u < 8; ++u) {
            float4 hk4 = hkp[sl + 8 * u];
            float4 q4 = *(const float4*)&hqs[sl * 4 + 32 * u];
            float hx = fmaxf(fmaf(dij, wd4[u].x, q4.x + hk4.x), 0.0f);
            float hy = fmaxf(fmaf(dij, wd4[u].y, q4.y + hk4.y), 0.0f);
            float hz = fmaxf(fmaf(dij, wd4[u].z, q4.z + hk4.z), 0.0f);
            float hw_ = fmaxf(fmaf(dij, wd4[u].w, q4.w + hk4.w), 0.0f);
            acc = fmaf(hx, e24[u].x, acc);
            acc = fmaf(hy, e24[u].y, acc);
            acc = fmaf(hz, e24[u].z, acc);
            acc = fmaf(hw_, e24[u].w, acc);
        }
        acc = red8(acc);
        if (sl == 0) sc[jj] = acc + eb2v;
    }
    __syncthreads();

    // block softmax over 512
    float m = fmaxf(sc[t], sc[t + 256]);
    m = rmax32(m);
    if (l == 0) redm[w] = m;
    __syncthreads();
    m = redm[0];
#pragma unroll
    for (int ww = 1; ww < 8; ++ww) m = fmaxf(m, redm[ww]);
    float e0 = __expf(sc[t] - m), e1v = __expf(sc[t + 256] - m);
    sc[t] = e0; sc[t + 256] = e1v;
    float s = red32(e0 + e1v);
    if (l == 0) reds[w] = s;
    __syncthreads();
    s = 0.0f;
#pragma unroll
    for (int ww = 0; ww < 8; ++ww) s += reds[ww];
    float invv = 1.0f / s;

    if (edgeOut != nullptr) {
        float* eo = edgeOut + idx * 512;
        eo[t] = sc[t] * invv;
        eo[t + 256] = sc[t + 256] * invv;
    }
    if (!doMLP) return;

    // agg
    float a = 0.0f;
    for (int j = w; j < 512; j += 8) a = fmaf(sc[j], gYVB[(b * 512 + j) * 32 + l], a);
    part[t] = a;
    __syncthreads();
    if (t < 32) {
        float ss = 0.0f;
#pragma unroll
        for (int ww = 0; ww < 8; ++ww) ss += part[ww * 32 + t];
        zz[32 + t] = ss * invv;
        zz[t] = gX[idx * 32 + t];
    }
    __syncthreads();

    float acc = nb1[t];
#pragma unroll 8
    for (int c = 0; c < 64; ++c) acc = fmaf(zz[c], nW1[c * 256 + t], acc);
    hh[t] = fmaxf(acc, 0.0f);
    __syncthreads();
    float p = 0.0f;
#pragma unroll 8
    for (int j = w * 32; j < w * 32 + 32; ++j) p = fmaf(hh[j], nW2[j * 32 + l], p);
    part[t] = p;
    __syncthreads();
    if (t < 32) {
        float ss = nb2[t];
#pragma unroll
        for (int ww = 0; ww < 8; ++ww) ss += part[ww * 32 + t];
        gX[idx * 32 + t] = zz[t] + ss;
    }
}

// ---------------------------------------------------------------------------
extern "C" void kernel_launch(void* const* d_in, const int* in_sizes, int n_in,
                              void* d_out, int out_size) {
    const float* agent_pos    = (const float*)d_in[0];
    const float* frontier_pos = (const float*)d_in[1];
    const float* past_agent   = (const float*)d_in[2];
    const float* past_goal    = (const float*)d_in[3];
    const float* dis_rp       = (const float*)d_in[4];
    const float* dis_fp       = (const float*)d_in[5];
    const float* dis_rf       = (const float*)d_in[6];
    const float* ni_W1        = (const float*)d_in[7];
    const float* ni_b1        = (const float*)d_in[8];
    const float* ni_W2        = (const float*)d_in[9];
    const float* ni_b2        = (const float*)d_in[10];
    const float* Wq           = (const float*)d_in[11];
    const float* bq           = (const float*)d_in[12];
    const float* Wk           = (const float*)d_in[13];
    const float* bk           = (const float*)d_in[14];
    const float* Wv           = (const float*)d_in[15];
    const float* bv           = (const float*)d_in[16];
    const float* nW1          = (const float*)d_in[17];
    const float* nb1          = (const float*)d_in[18];
    const float* nW2          = (const float*)d_in[19];
    const float* nb2          = (const float*)d_in[20];
    const float* eW1          = (const float*)d_in[21];
    const float* eb1          = (const float*)d_in[22];
    const float* eW2          = (const float*)d_in[23];
    const float* eb2          = (const float*)d_in[24];
    float* edge = (float*)d_out;

    k_init<<<776, 256>>>(agent_pos, frontier_pos, past_agent, past_goal,
                         ni_W1, ni_b1, ni_W2, ni_b2);

    for (int b3 = 0; b3 < 3; ++b3) {
        const float* Wq_b  = Wq  + b3 * 32 * 32;
        const float* bq_b  = bq  + b3 * 32;
        const float* Wk_b  = Wk  + b3 * 32 * 32;
        const float* bk_b  = bk  + b3 * 32;
        const float* Wv_b  = Wv  + b3 * 32 * 32;
        const float* bv_b  = bv  + b3 * 32;
        const float* nW1_b = nW1 + b3 * 64 * 256;
        const float* nb1_b = nb1 + b3 * 256;
        const float* nW2_b = nW2 + b3 * 256 * 32;
        const float* nb2_b = nb2 + b3 * 32;
        const float* eW1_b = eW1 + b3 * 65 * 256;
        const float* eb1_b = eb1 + b3 * 256;
        const float* eW2_b = eW2 + b3 * 256;
        const float* eb2_b = eb2 + b3;

        k_qkv<<<776, 256>>>(Wq_b, bq_b, Wk_b, bk_b, Wv_b, bv_b);
        k_intra<<<776, 256>>>(nW1_b, nb1_b, nW2_b, nb2_b,
                              Wk_b, bk_b, Wv_b, bv_b, eW1_b, eb1_b);
        k_mainA<<<520, 256>>>(dis_rp, dis_fp,
                              Wq_b, bq_b, Wk_b, bk_b, Wv_b, bv_b,
                              eW1_b, eb1_b, eW2_b, eb2_b,
                              nW1_b, nb1_b, nW2_b, nb2_b);
        float* eo = (b3 == 2) ? edge : nullptr;
        int doMLP = (b3 == 2) ? 0 : 1;
        k_mainB<<<64, 256>>>(dis_rf, Wq_b, bq_b,
                             eW1_b, eW2_b, eb2_b,
                             nW1_b, nb1_b, nW2_b, nb2_b, eo, doMLP);
    }
}